// round 1
// baseline (speedup 1.0000x reference)
#include <cuda_runtime.h>

// ---------------------------------------------------------------------------
// MechanisticNRTLLoss: B=1e6 elements, 3-component NRTL, reduce to scalar.
// Inputs (metadata order): pred (B,6) f32, target (B,6) f32, T (B,) f32,
//                          g (B,3,3) f32, dirs (2,B,3) f32, noise (4,B,3) f32
// Output: scalar f32 loss.
// ---------------------------------------------------------------------------

#define B_N      1000000
#define THREADS  256
#define NBLOCKS  ((B_N + THREADS - 1) / THREADS)   // 3907

__device__ float g_partials[4096];

__device__ __forceinline__ float clipf(float v, float lo, float hi) {
    return fminf(fmaxf(v, lo), hi);
}

// renorm3: clamp >=0, normalize to sum 1 (sum clamped to EPS)
__device__ __forceinline__ void renorm3(float x0, float x1, float x2, float out[3]) {
    x0 = fmaxf(x0, 0.0f);
    x1 = fmaxf(x1, 0.0f);
    x2 = fmaxf(x2, 0.0f);
    float s  = x0 + x1 + x2;
    float rs = __fdividef(1.0f, fmaxf(s, 1e-12f));
    out[0] = x0 * rs;
    out[1] = x1 * rs;
    out[2] = x2 * rs;
}

// NRTL ln_gamma for one composition. tau/G precomputed (row-major [j*3+i] = tau_{ji}).
__device__ __forceinline__ void nrtl_ln_gamma(const float x[3],
                                              const float tau[9],
                                              const float G[9],
                                              float out[3]) {
    float rden[3], ad[3];
    // denom_i = sum_j x_j * G[j][i] ;  A_i = sum_j x_j * tau[j][i] * G[j][i]
#pragma unroll
    for (int i = 0; i < 3; i++) {
        float d = 0.0f, a = 0.0f;
#pragma unroll
        for (int j = 0; j < 3; j++) {
            float gg = G[j * 3 + i];
            float xg = x[j] * gg;
            d += xg;
            a = fmaf(xg, tau[j * 3 + i], a);
        }
        d = fmaxf(d, 1e-12f);
        rden[i] = __fdividef(1.0f, d);
        ad[i]   = a * rden[i];           // A_i / denom_i  (== term1_i)
    }
    // term2_i = sum_j x_j * G[i][j] * rden_j * (tau[i][j] - ad_j)
#pragma unroll
    for (int i = 0; i < 3; i++) {
        float t2 = 0.0f;
#pragma unroll
        for (int j = 0; j < 3; j++) {
            float w = x[j] * G[i * 3 + j] * rden[j];
            t2 = fmaf(w, tau[i * 3 + j] - ad[j], t2);
        }
        out[i] = clipf(ad[i] + t2, -20.0f, 20.0f);
    }
}

__global__ void __launch_bounds__(THREADS)
nrtl_loss_main(const float* __restrict__ pred,
               const float* __restrict__ target,
               const float* __restrict__ T,
               const float* __restrict__ g,
               const float* __restrict__ dirs,
               const float* __restrict__ noise) {
    const int b = blockIdx.x * blockDim.x + threadIdx.x;

    float contrib = 0.0f;
    if (b < B_N) {
        // ---------------- supervised MSE (sum of 6 squares) ----------------
        float p[6];
        float sup = 0.0f;
#pragma unroll
        for (int k = 0; k < 6; k++) {
            p[k] = pred[b * 6 + k];
            float d = p[k] - target[b * 6 + k];
            sup = fmaf(d, d, sup);
        }

        // ---------------- tau / G (shared across all NRTL evals) -----------
        float Tc   = fmaxf(T[b], 1.0f);
        float rRT  = __fdividef(1.0f, 8.314462618f * Tc);
        float tau[9], G[9];
#pragma unroll
        for (int k = 0; k < 9; k++) {
            float t = clipf(g[b * 9 + k] * rRT, -10.0f, 10.0f);
            tau[k] = t;
            G[k]   = __expf(-0.3f * t);
        }

        // ---------------- xE / xR + ln gamma --------------------------------
        float xE[3], xR[3], lngE[3], lngR[3];
        renorm3(p[0], p[1], p[2], xE);
        renorm3(p[3], p[4], p[5], xR);
        nrtl_ln_gamma(xE, tau, G, lngE);
        nrtl_ln_gamma(xR, tau, G, lngR);

        float lnxE[3], lnxR[3];
#pragma unroll
        for (int k = 0; k < 3; k++) {
            lnxE[k] = __logf(fmaxf(xE[k], 1e-12f));
            lnxR[k] = __logf(fmaxf(xR[k], 1e-12f));
        }

        // chemical potential residual
        float phy = 0.0f;
#pragma unroll
        for (int k = 0; k < 3; k++) {
            float r = (lnxE[k] + lngE[k]) - (lnxR[k] + lngR[k]);
            phy = fmaf(r, r, phy);
        }

        // ---------------- Gibbs-Duhem FD penalty (2 directions) -------------
        float gd_sum = 0.0f;
#pragma unroll
        for (int d = 0; d < 2; d++) {
            float dv[3];
#pragma unroll
            for (int k = 0; k < 3; k++)
                dv[k] = dirs[((size_t)d * B_N + b) * 3 + k];

            float xp[3], xm[3], lgp[3], lgm[3];
            renorm3(xE[0] + 1e-4f * dv[0], xE[1] + 1e-4f * dv[1], xE[2] + 1e-4f * dv[2], xp);
            renorm3(xE[0] - 1e-4f * dv[0], xE[1] - 1e-4f * dv[1], xE[2] - 1e-4f * dv[2], xm);
            nrtl_ln_gamma(xp, tau, G, lgp);
            nrtl_ln_gamma(xm, tau, G, lgm);

            float gd = 0.0f;
#pragma unroll
            for (int k = 0; k < 3; k++)
                gd = fmaf(xE[k], (lgp[k] - lgm[k]) * 5000.0f, gd);  // /(2*1e-4)
            gd_sum = fmaf(gd, gd, gd_sum);
        }

        // ---------------- TPD penalty (4 trials) ----------------------------
        float tpd_sum = 0.0f;
#pragma unroll
        for (int t = 0; t < 4; t++) {
            float w[3];
            renorm3(xE[0] + noise[((size_t)t * B_N + b) * 3 + 0],
                    xE[1] + noise[((size_t)t * B_N + b) * 3 + 1],
                    xE[2] + noise[((size_t)t * B_N + b) * 3 + 2], w);
            float lngw[3];
            nrtl_ln_gamma(w, tau, G, lngw);

            float tpd = 0.0f;
#pragma unroll
            for (int k = 0; k < 3; k++) {
                float lnw = __logf(fmaxf(w[k], 1e-12f));
                tpd = fmaf(w[k], (lnw + lngw[k]) - (lnxE[k] + lngE[k]), tpd);
            }
            tpd_sum += fmaxf(-tpd, 0.0f);   // MARGIN = 0
        }

        // per-element combined contribution (loss = mean over B of contrib)
        contrib = sup * (1.0f / 6.0f)
                + phy * (1.0f / 3.0f)
                + 0.1f * gd_sum * 0.5f
                + 0.1f * tpd_sum * 0.25f;
    }

    // ---------------- deterministic block reduction -------------------------
    __shared__ float sdata[THREADS / 32];
    // warp tree
#pragma unroll
    for (int off = 16; off > 0; off >>= 1)
        contrib += __shfl_down_sync(0xFFFFFFFFu, contrib, off);
    if ((threadIdx.x & 31) == 0)
        sdata[threadIdx.x >> 5] = contrib;
    __syncthreads();
    if (threadIdx.x < 32) {
        float v = (threadIdx.x < THREADS / 32) ? sdata[threadIdx.x] : 0.0f;
#pragma unroll
        for (int off = 4; off > 0; off >>= 1)
            v += __shfl_down_sync(0xFFFFFFFFu, v, off);
        if (threadIdx.x == 0)
            g_partials[blockIdx.x] = v;
    }
}

// Single-block deterministic final reduction (fixed strided order, double accum)
__global__ void __launch_bounds__(256)
nrtl_loss_final(float* __restrict__ out, int n) {
    __shared__ double sdata[256];
    double acc = 0.0;
    for (int i = threadIdx.x; i < n; i += 256)
        acc += (double)g_partials[i];
    sdata[threadIdx.x] = acc;
    __syncthreads();
#pragma unroll
    for (int s = 128; s > 0; s >>= 1) {
        if (threadIdx.x < s) sdata[threadIdx.x] += sdata[threadIdx.x + s];
        __syncthreads();
    }
    if (threadIdx.x == 0)
        out[0] = (float)(sdata[0] * (1.0 / (double)B_N));
}

extern "C" void kernel_launch(void* const* d_in, const int* in_sizes, int n_in,
                              void* d_out, int out_size) {
    const float* pred   = (const float*)d_in[0];
    const float* target = (const float*)d_in[1];
    const float* T      = (const float*)d_in[2];
    const float* g      = (const float*)d_in[3];
    const float* dirs   = (const float*)d_in[4];
    const float* noise  = (const float*)d_in[5];
    float* out = (float*)d_out;

    nrtl_loss_main<<<NBLOCKS, THREADS>>>(pred, target, T, g, dirs, noise);
    nrtl_loss_final<<<1, 256>>>(out, NBLOCKS);
}